// round 13
// baseline (speedup 1.0000x reference)
#include <cuda_runtime.h>
#include <cstdint>

// Problem constants (fixed by the reference)
#define BATCH      512
#define SEQ        200
#define HALF       100   // t-range per te_main block
#define EMB        256
#define NUM_SKILLS 300
#define D3         21    // CURVE_DIM//3

// Precomputed affine basis: traj[b,t,e] = qf*A[e] + att*B[e] + mast*C[e] + D[e]
__device__ __align__(16) float g_A[EMB];
__device__ __align__(16) float g_B[EMB];
__device__ __align__(16) float g_C[EMB];
__device__ __align__(16) float g_D[EMB];

// ---------------------------------------------------------------------------
// Precompute: warp-per-embedding-row, fully coalesced. 8 blocks x 256 threads.
// ---------------------------------------------------------------------------
__global__ __launch_bounds__(256) void te_precompute(const float* __restrict__ skill_w,
                                                     const float* __restrict__ skill_b,
                                                     const float* __restrict__ att_w,
                                                     const float* __restrict__ att_b,
                                                     const float* __restrict__ mast_w,
                                                     const float* __restrict__ mast_b,
                                                     const float* __restrict__ proj_w,
                                                     const float* __restrict__ proj_b) {
    const int lane = threadIdx.x & 31;
    const int wid  = (blockIdx.x * blockDim.x + threadIdx.x) >> 5;  // global warp 0..63

    const int   c1  = lane + 32;
    const float w0  = (lane < D3) ? skill_w[lane] : att_w[lane - D3];
    const float bw0 = (lane < D3) ? skill_b[lane] : att_b[lane - D3];
    const float w1  = (c1 < 2 * D3) ? att_w[c1 - D3] : mast_w[c1 - 2 * D3];
    const float bw1 = (c1 < 2 * D3) ? att_b[c1 - D3] : mast_b[c1 - 2 * D3];
    const bool  seg0_is_a = (lane < D3);
    const bool  seg1_is_b = (c1 < 2 * D3);

#pragma unroll
    for (int j = 0; j < 4; j++) {
        const int e = wid * 4 + j;
        const float x0 = proj_w[e * 64 + lane];   // coalesced
        const float x1 = proj_w[e * 64 + c1];     // coalesced

        const float t0 = w0 * x0;
        const float t1 = w1 * x1;
        float pa = seg0_is_a ? t0 : 0.f;
        float pb = (seg0_is_a ? 0.f : t0) + (seg1_is_b ? t1 : 0.f);
        float pc = seg1_is_b ? 0.f : t1;
        float pd = fmaf(bw0, x0, bw1 * x1);

#pragma unroll
        for (int off = 16; off >= 1; off >>= 1) {
            pa += __shfl_xor_sync(0xffffffffu, pa, off);
            pb += __shfl_xor_sync(0xffffffffu, pb, off);
            pc += __shfl_xor_sync(0xffffffffu, pc, off);
            pd += __shfl_xor_sync(0xffffffffu, pd, off);
        }
        if (lane == 0) {
            g_A[e] = pa;
            g_B[e] = pb;
            g_C[e] = pc;
            g_D[e] = pd + proj_b[e];
        }
    }
}

// ---------------------------------------------------------------------------
// Main: 1024 blocks (2 per batch row) x 256 threads, 8 blocks/SM (one wave).
// Phase 1: running counts by direct counting (parallel over t).
// Phase 2: 4 t-subgroups x 64 lanes; each lane owns a float4 of the 256-wide
//          row -> 1KB fully-coalesced stores per t.
//
// Stores carry an L2::evict_last cache-policy (createpolicy + cache_hint —
// the sm_100-legal encoding for arbitrary vector widths): the 105MB output
// fits in the 126MB L2, so pinning dirty output lines at lowest eviction
// priority lets each graph replay re-dirty the SAME resident lines, removing
// the steady-state DRAM writeback drain (~26.5us/replay cap) and the LTS
// eviction-read pass.
// ---------------------------------------------------------------------------
__global__ __launch_bounds__(256, 8) void te_main(const int* __restrict__ q,
                                                  const int* __restrict__ r,
                                                  float* __restrict__ out) {
    __shared__ int sq[SEQ];
    __shared__ int sr[SEQ];
    __shared__ __align__(16) float4 s_scal[HALF];  // {qf, att, mast, valid}

    const int b   = blockIdx.x >> 1;
    const int t0  = (blockIdx.x & 1) * HALF;
    const int tid = threadIdx.x;

    if (tid < SEQ) {
        sq[tid] = q[b * SEQ + tid];
        sr[tid] = r[b * SEQ + tid];
    }
    __syncthreads();

    // Phase 1: attempts[t] = #{t' <= t : valid(t') && q[t']==q[t]}, correct w/ r.
    if (tid < HALF) {
        const int t  = t0 + tid;
        const int qt = sq[t];
        int att = 0, cor = 0;
        for (int tp = 0; tp <= t; tp++) {
            int qp = sq[tp];                    // warp-broadcast smem read
            if ((unsigned)qp < NUM_SKILLS && qp == qt) {
                att += 1;
                cor += sr[tp];
            }
        }
        const float v  = ((unsigned)qt < NUM_SKILLS) ? 1.0f : 0.0f;
        const float af = (float)att;
        s_scal[tid] = make_float4(v * (float)qt,
                                  v * af,
                                  v * ((float)cor / fmaxf(af, 1.0f)),
                                  v);
    }
    __syncthreads();

    // Phase 2
    const int lane = tid & 63;   // float4 index within the 256-wide row
    const int tg   = tid >> 6;   // 0..3

    const float4 A  = reinterpret_cast<const float4*>(g_A)[lane];
    const float4 Bv = reinterpret_cast<const float4*>(g_B)[lane];
    const float4 C  = reinterpret_cast<const float4*>(g_C)[lane];
    const float4 D  = reinterpret_cast<const float4*>(g_D)[lane];

    // L2 evict_last policy (fraction 1.0) — applied to every output store.
    uint64_t pol;
    asm volatile("createpolicy.fractional.L2::evict_last.b64 %0, 1.0;"
                 : "=l"(pol));

    float4* __restrict__ p = reinterpret_cast<float4*>(out)
                           + (size_t)(b * SEQ + t0 + tg) * (EMB / 4) + lane;

#pragma unroll 5
    for (int i = tg; i < HALF; i += 4, p += 4 * (EMB / 4)) {
        const float4 s = s_scal[i];   // one LDS.128, broadcast within warp
        float4 o;
        o.x = fmaf(s.x, A.x, fmaf(s.y, Bv.x, fmaf(s.z, C.x, s.w * D.x)));
        o.y = fmaf(s.x, A.y, fmaf(s.y, Bv.y, fmaf(s.z, C.y, s.w * D.y)));
        o.z = fmaf(s.x, A.z, fmaf(s.y, Bv.z, fmaf(s.z, C.z, s.w * D.z)));
        o.w = fmaf(s.x, A.w, fmaf(s.y, Bv.w, fmaf(s.z, C.w, s.w * D.w)));
        asm volatile("st.global.L2::cache_hint.v4.f32 [%0], {%1, %2, %3, %4}, %5;"
                     :: "l"(p), "f"(o.x), "f"(o.y), "f"(o.z), "f"(o.w), "l"(pol)
                     : "memory");
    }
}

extern "C" void kernel_launch(void* const* d_in, const int* in_sizes, int n_in,
                              void* d_out, int out_size) {
    // metadata order: q, r, qry, skill_w, skill_b, att_w, att_b,
    //                 mast_w, mast_b, proj_w, proj_b
    const int*   q       = (const int*)d_in[0];
    const int*   r       = (const int*)d_in[1];
    // d_in[2] = qry — unused by the reference
    const float* skill_w = (const float*)d_in[3];
    const float* skill_b = (const float*)d_in[4];
    const float* att_w   = (const float*)d_in[5];
    const float* att_b   = (const float*)d_in[6];
    const float* mast_w  = (const float*)d_in[7];
    const float* mast_b  = (const float*)d_in[8];
    const float* proj_w  = (const float*)d_in[9];
    const float* proj_b  = (const float*)d_in[10];
    float* out = (float*)d_out;

    te_precompute<<<8, 256>>>(skill_w, skill_b, att_w, att_b,
                              mast_w, mast_b, proj_w, proj_b);
    te_main<<<BATCH * 2, 256>>>(q, r, out);
}

// round 14
// speedup vs baseline: 1.0132x; 1.0132x over previous
#include <cuda_runtime.h>
#include <cstdint>

// Problem constants (fixed by the reference)
#define BATCH      512
#define SEQ        200
#define HALF       100   // t-range per te_main block
#define EMB        256
#define NUM_SKILLS 300
#define D3         21    // CURVE_DIM//3

// Precomputed affine basis: traj[b,t,e] = qf*A[e] + att*B[e] + mast*C[e] + D[e]
__device__ __align__(16) float g_A[EMB];
__device__ __align__(16) float g_B[EMB];
__device__ __align__(16) float g_C[EMB];
__device__ __align__(16) float g_D[EMB];

// ---- packed f32x2 helpers (Blackwell; only reachable via PTX) ----
#define PACK2(out, v) \
    asm("mov.b64 %0, {%1, %1};" : "=l"(out) : "f"(v))
#define MUL2(out, a, b) \
    asm("mul.rn.f32x2 %0, %1, %2;" : "=l"(out) : "l"(a), "l"(b))
#define FMA2(out, a, b, c) \
    asm("fma.rn.f32x2 %0, %1, %2, %3;" : "=l"(out) : "l"(a), "l"(b), "l"(c))

// ---------------------------------------------------------------------------
// Precompute: warp-per-embedding-row, fully coalesced. 8 blocks x 256 threads.
// ---------------------------------------------------------------------------
__global__ __launch_bounds__(256) void te_precompute(const float* __restrict__ skill_w,
                                                     const float* __restrict__ skill_b,
                                                     const float* __restrict__ att_w,
                                                     const float* __restrict__ att_b,
                                                     const float* __restrict__ mast_w,
                                                     const float* __restrict__ mast_b,
                                                     const float* __restrict__ proj_w,
                                                     const float* __restrict__ proj_b) {
    const int lane = threadIdx.x & 31;
    const int wid  = (blockIdx.x * blockDim.x + threadIdx.x) >> 5;  // global warp 0..63

    const int   c1  = lane + 32;
    const float w0  = (lane < D3) ? skill_w[lane] : att_w[lane - D3];
    const float bw0 = (lane < D3) ? skill_b[lane] : att_b[lane - D3];
    const float w1  = (c1 < 2 * D3) ? att_w[c1 - D3] : mast_w[c1 - 2 * D3];
    const float bw1 = (c1 < 2 * D3) ? att_b[c1 - D3] : mast_b[c1 - 2 * D3];
    const bool  seg0_is_a = (lane < D3);
    const bool  seg1_is_b = (c1 < 2 * D3);

#pragma unroll
    for (int j = 0; j < 4; j++) {
        const int e = wid * 4 + j;
        const float x0 = proj_w[e * 64 + lane];   // coalesced
        const float x1 = proj_w[e * 64 + c1];     // coalesced

        const float t0 = w0 * x0;
        const float t1 = w1 * x1;
        float pa = seg0_is_a ? t0 : 0.f;
        float pb = (seg0_is_a ? 0.f : t0) + (seg1_is_b ? t1 : 0.f);
        float pc = seg1_is_b ? 0.f : t1;
        float pd = fmaf(bw0, x0, bw1 * x1);

#pragma unroll
        for (int off = 16; off >= 1; off >>= 1) {
            pa += __shfl_xor_sync(0xffffffffu, pa, off);
            pb += __shfl_xor_sync(0xffffffffu, pb, off);
            pc += __shfl_xor_sync(0xffffffffu, pc, off);
            pd += __shfl_xor_sync(0xffffffffu, pd, off);
        }
        if (lane == 0) {
            g_A[e] = pa;
            g_B[e] = pb;
            g_C[e] = pc;
            g_D[e] = pd + proj_b[e];
        }
    }
}

// ---------------------------------------------------------------------------
// Main: 1024 blocks (2 per batch row) x 256 threads, 8 blocks/SM (one wave).
// Phase 1: running counts by direct counting (parallel over t).
// Phase 2: packed f32x2 math — 8 ops per float4 instead of 16 scalar FFMAs —
//          then 1KB fully-coalesced streaming stores per t.
// ---------------------------------------------------------------------------
__global__ __launch_bounds__(256, 8) void te_main(const int* __restrict__ q,
                                                  const int* __restrict__ r,
                                                  float* __restrict__ out) {
    __shared__ int sq[SEQ];
    __shared__ int sr[SEQ];
    __shared__ __align__(16) float4 s_scal[HALF];  // {qf, att, mast, valid}

    const int b   = blockIdx.x >> 1;
    const int t0  = (blockIdx.x & 1) * HALF;
    const int tid = threadIdx.x;

    if (tid < SEQ) {
        sq[tid] = q[b * SEQ + tid];
        sr[tid] = r[b * SEQ + tid];
    }
    __syncthreads();

    // Phase 1: attempts[t] = #{t' <= t : valid(t') && q[t']==q[t]}, correct w/ r.
    if (tid < HALF) {
        const int t  = t0 + tid;
        const int qt = sq[t];
        int att = 0, cor = 0;
        for (int tp = 0; tp <= t; tp++) {
            int qp = sq[tp];                    // warp-broadcast smem read
            if ((unsigned)qp < NUM_SKILLS && qp == qt) {
                att += 1;
                cor += sr[tp];
            }
        }
        const float v  = ((unsigned)qt < NUM_SKILLS) ? 1.0f : 0.0f;
        const float af = (float)att;
        s_scal[tid] = make_float4(v * (float)qt,
                                  v * af,
                                  v * ((float)cor / fmaxf(af, 1.0f)),
                                  v);
    }
    __syncthreads();

    // Phase 2
    const int lane = tid & 63;   // float4 index within the 256-wide row
    const int tg   = tid >> 6;   // 0..3

    // Basis as packed f32x2 pairs: {e0,e1} and {e2,e3} of this lane's float4.
    const ulonglong2 A2 = reinterpret_cast<const ulonglong2*>(g_A)[lane];
    const ulonglong2 B2 = reinterpret_cast<const ulonglong2*>(g_B)[lane];
    const ulonglong2 C2 = reinterpret_cast<const ulonglong2*>(g_C)[lane];
    const ulonglong2 D2 = reinterpret_cast<const ulonglong2*>(g_D)[lane];

    char* __restrict__ p = reinterpret_cast<char*>(out)
                         + ((size_t)(b * SEQ + t0 + tg) * EMB + lane * 4) * 4;

#pragma unroll 5
    for (int i = tg; i < HALF; i += 4, p += 4 * EMB * 4) {
        const float4 s = s_scal[i];   // one LDS.128, broadcast within warp
        uint64_t sx2, sy2, sz2, sw2;
        PACK2(sx2, s.x);
        PACK2(sy2, s.y);
        PACK2(sz2, s.z);
        PACK2(sw2, s.w);

        uint64_t o01, o23;
        // o = ((sw*D + sz*C)... chain: mul, fma, fma, fma — rn, identical
        // rounding to the scalar FFMA chain.
        MUL2(o01, sw2, D2.x);
        FMA2(o01, sz2, C2.x, o01);
        FMA2(o01, sy2, B2.x, o01);
        FMA2(o01, sx2, A2.x, o01);

        MUL2(o23, sw2, D2.y);
        FMA2(o23, sz2, C2.y, o23);
        FMA2(o23, sy2, B2.y, o23);
        FMA2(o23, sx2, A2.y, o23);

        // 16B streaming store (write-once output).
        asm volatile("st.global.cs.v2.b64 [%0], {%1, %2};"
                     :: "l"(p), "l"(o01), "l"(o23)
                     : "memory");
    }
}

extern "C" void kernel_launch(void* const* d_in, const int* in_sizes, int n_in,
                              void* d_out, int out_size) {
    // metadata order: q, r, qry, skill_w, skill_b, att_w, att_b,
    //                 mast_w, mast_b, proj_w, proj_b
    const int*   q       = (const int*)d_in[0];
    const int*   r       = (const int*)d_in[1];
    // d_in[2] = qry — unused by the reference
    const float* skill_w = (const float*)d_in[3];
    const float* skill_b = (const float*)d_in[4];
    const float* att_w   = (const float*)d_in[5];
    const float* att_b   = (const float*)d_in[6];
    const float* mast_w  = (const float*)d_in[7];
    const float* mast_b  = (const float*)d_in[8];
    const float* proj_w  = (const float*)d_in[9];
    const float* proj_b  = (const float*)d_in[10];
    float* out = (float*)d_out;

    te_precompute<<<8, 256>>>(skill_w, skill_b, att_w, att_b,
                              mast_w, mast_b, proj_w, proj_b);
    te_main<<<BATCH * 2, 256>>>(q, r, out);
}